// round 1
// baseline (speedup 1.0000x reference)
#include <cuda_runtime.h>
#include <cuda_bf16.h>
#include <math.h>

// Problem constants
#define BATCH   16
#define SEQ     1024
#define TOKENS  (BATCH*SEQ)     // 16384
#define CDIM    768
#define C3      (3*CDIM)        // 2304
#define HID     3072
#define NHEADS  12
#define HDIM    64
#define LN_EPS  1e-5f

// ---------------------------------------------------------------------------
// Scratch (device globals; allocation APIs are forbidden)
// ---------------------------------------------------------------------------
__device__ float g_xn1 [ (size_t)TOKENS * CDIM ];   // LN1 output
__device__ float g_qkv [ (size_t)TOKENS * C3   ];   // qkv projection
__device__ float g_attn[ (size_t)TOKENS * CDIM ];   // attention output (pre-proj)
__device__ float g_x2  [ (size_t)TOKENS * CDIM ];   // x + attn proj (residual 1)
__device__ float g_hn  [ (size_t)TOKENS * CDIM ];   // LN2 output
__device__ float g_h1  [ (size_t)TOKENS * HID  ];   // gelu(fc1)

// ---------------------------------------------------------------------------
// LayerNorm: one block (256 thr) per row of 768
// ---------------------------------------------------------------------------
__global__ __launch_bounds__(256)
void ln_kernel(const float* __restrict__ x, const float* __restrict__ gam,
               const float* __restrict__ bet, float* __restrict__ out)
{
    int row = blockIdx.x;
    int tid = threadIdx.x;
    const float* xr = x + (size_t)row * CDIM;

    float v0 = xr[tid], v1 = xr[tid + 256], v2 = xr[tid + 512];

    __shared__ float red[8];
    __shared__ float mu_s, rs_s;

    float s = v0 + v1 + v2;
    #pragma unroll
    for (int off = 16; off > 0; off >>= 1) s += __shfl_xor_sync(0xffffffffu, s, off);
    if ((tid & 31) == 0) red[tid >> 5] = s;
    __syncthreads();
    if (tid == 0) {
        float t = 0.f;
        #pragma unroll
        for (int i = 0; i < 8; i++) t += red[i];
        mu_s = t * (1.0f / CDIM);
    }
    __syncthreads();
    float mu = mu_s;
    float d0 = v0 - mu, d1 = v1 - mu, d2 = v2 - mu;

    float q = d0*d0 + d1*d1 + d2*d2;
    #pragma unroll
    for (int off = 16; off > 0; off >>= 1) q += __shfl_xor_sync(0xffffffffu, q, off);
    __syncthreads();                      // red reuse safety
    if ((tid & 31) == 0) red[tid >> 5] = q;
    __syncthreads();
    if (tid == 0) {
        float t = 0.f;
        #pragma unroll
        for (int i = 0; i < 8; i++) t += red[i];
        rs_s = rsqrtf(t * (1.0f / CDIM) + LN_EPS);
    }
    __syncthreads();
    float rs = rs_s;

    float* orow = out + (size_t)row * CDIM;
    orow[tid      ] = d0 * rs * gam[tid      ] + bet[tid      ];
    orow[tid + 256] = d1 * rs * gam[tid + 256] + bet[tid + 256];
    orow[tid + 512] = d2 * rs * gam[tid + 512] + bet[tid + 512];
}

// ---------------------------------------------------------------------------
// SGEMM: C[M,N] = A[M,K] @ B[K,N] + bias[N]  (+ GELU) (+ residual)
// 128x128 tile, BK=8, 256 threads, 8x8 per thread.
// M,N,K all multiples of the tile sizes for every call here.
// ---------------------------------------------------------------------------
template<bool DO_GELU, bool DO_RESID>
__global__ __launch_bounds__(256)
void sgemm128(const float* __restrict__ A, const float* __restrict__ B,
              const float* __restrict__ bias, const float* __restrict__ resid,
              float* __restrict__ C, int M, int N, int K)
{
    __shared__ float As[8][128];
    __shared__ float Bs[8][128];

    int tid  = threadIdx.x;
    int row0 = blockIdx.y * 128;
    int col0 = blockIdx.x * 128;
    int ty = tid >> 4;        // 0..15
    int tx = tid & 15;        // 0..15

    // global load mapping
    int arow = tid >> 1;              // 0..127
    int acol = (tid & 1) * 4;         // 0 or 4
    int brow = tid >> 5;              // 0..7
    int bcol = (tid & 31) * 4;        // 0..124

    const float* Aptr = A + (size_t)(row0 + arow) * K + acol;
    const float* Bptr = B + (size_t)brow * N + col0 + bcol;

    float acc[8][8];
    #pragma unroll
    for (int i = 0; i < 8; i++)
        #pragma unroll
        for (int j = 0; j < 8; j++) acc[i][j] = 0.f;

    for (int k0 = 0; k0 < K; k0 += 8) {
        float4 av = *(const float4*)(Aptr + k0);
        float4 bv = *(const float4*)(Bptr + (size_t)k0 * N);
        As[acol + 0][arow] = av.x;
        As[acol + 1][arow] = av.y;
        As[acol + 2][arow] = av.z;
        As[acol + 3][arow] = av.w;
        *(float4*)&Bs[brow][bcol] = bv;
        __syncthreads();

        #pragma unroll
        for (int k = 0; k < 8; k++) {
            float4 a0 = *(const float4*)&As[k][ty * 8];
            float4 a1 = *(const float4*)&As[k][ty * 8 + 4];
            float4 b0 = *(const float4*)&Bs[k][tx * 8];
            float4 b1 = *(const float4*)&Bs[k][tx * 8 + 4];
            float ar[8] = {a0.x,a0.y,a0.z,a0.w,a1.x,a1.y,a1.z,a1.w};
            float br[8] = {b0.x,b0.y,b0.z,b0.w,b1.x,b1.y,b1.z,b1.w};
            #pragma unroll
            for (int i = 0; i < 8; i++)
                #pragma unroll
                for (int j = 0; j < 8; j++)
                    acc[i][j] = fmaf(ar[i], br[j], acc[i][j]);
        }
        __syncthreads();
    }

    // epilogue
    #pragma unroll
    for (int i = 0; i < 8; i++) {
        int r = row0 + ty * 8 + i;
        size_t base = (size_t)r * N + col0 + tx * 8;
        #pragma unroll
        for (int j = 0; j < 8; j++) {
            float v = acc[i][j] + bias[col0 + tx * 8 + j];
            if (DO_GELU) {
                v = 0.5f * v * (1.0f + erff(v * 0.70710678118654752f));
            }
            if (DO_RESID) {
                v += resid[base + j];
            }
            C[base + j] = v;
        }
    }
}

// ---------------------------------------------------------------------------
// Flash attention (fp32): one block per (64-query tile, b*h).
// qkv layout: [tok, 3*C] with q at col h*64+d, k at 768+h*64+d, v at 1536+...
// ---------------------------------------------------------------------------
#define ATTN_SMEM_FLOATS (64*65 /*Qt*/ + 64*65 /*Kt*/ + 64*64 /*Vs*/ + 64*65 /*Ps*/ + 3*64)
#define ATTN_SMEM_BYTES  (ATTN_SMEM_FLOATS * 4)

__global__ __launch_bounds__(256)
void attn_kernel(const float* __restrict__ qkv, float* __restrict__ outp)
{
    extern __shared__ float sm[];
    float* Qt   = sm;                    // [64 k][65]  (transposed: Qt[d][q])
    float* Kt   = Qt + 64 * 65;          // Kt[d][n]
    float* Vs   = Kt + 64 * 65;          // Vs[n][d], stride 64
    float* Ps   = Vs + 64 * 64;          // scores/probs [q][65]
    float* mrow = Ps + 64 * 65;          // 64
    float* lrow = mrow + 64;
    float* arow = lrow + 64;

    int tid = threadIdx.x;
    int qb  = blockIdx.x * 64;
    int bh  = blockIdx.y;
    int b   = bh / NHEADS;
    int h   = bh % NHEADS;

    const float* base = qkv + (size_t)b * SEQ * C3 + h * HDIM;

    // load Q tile transposed
    for (int idx = tid; idx < 4096; idx += 256) {
        int n = idx >> 6, d = idx & 63;
        Qt[d * 65 + n] = base[(size_t)(qb + n) * C3 + d];
    }
    if (tid < 64) { mrow[tid] = -1e30f; lrow[tid] = 0.f; }

    int ty = tid >> 4, tx = tid & 15;
    float o[4][4];
    #pragma unroll
    for (int i = 0; i < 4; i++)
        #pragma unroll
        for (int j = 0; j < 4; j++) o[i][j] = 0.f;

    __syncthreads();

    for (int kt = 0; kt < SEQ / 64; kt++) {
        int kb = kt * 64;
        // load K (transposed) + V tiles
        for (int idx = tid; idx < 4096; idx += 256) {
            int n = idx >> 6, d = idx & 63;
            size_t roff = (size_t)(kb + n) * C3;
            Kt[d * 65 + n] = base[roff + CDIM + d];
            Vs[n * 64 + d] = base[roff + 2 * CDIM + d];
        }
        __syncthreads();

        // S = (Q @ K^T) * scale   -> Ps
        float s[4][4];
        #pragma unroll
        for (int i = 0; i < 4; i++)
            #pragma unroll
            for (int j = 0; j < 4; j++) s[i][j] = 0.f;

        for (int k = 0; k < 64; k++) {
            float qv[4], kv[4];
            #pragma unroll
            for (int i = 0; i < 4; i++) qv[i] = Qt[k * 65 + ty * 4 + i];
            #pragma unroll
            for (int j = 0; j < 4; j++) kv[j] = Kt[k * 65 + tx * 4 + j];
            #pragma unroll
            for (int i = 0; i < 4; i++)
                #pragma unroll
                for (int j = 0; j < 4; j++)
                    s[i][j] = fmaf(qv[i], kv[j], s[i][j]);
        }
        #pragma unroll
        for (int i = 0; i < 4; i++)
            #pragma unroll
            for (int j = 0; j < 4; j++)
                Ps[(ty * 4 + i) * 65 + tx * 4 + j] = s[i][j] * 0.125f;
        __syncthreads();

        // online softmax: 4 threads per row
        {
            int r = tid >> 2, sub = tid & 3;
            float mx = -1e30f;
            #pragma unroll
            for (int c = 0; c < 16; c++)
                mx = fmaxf(mx, Ps[r * 65 + sub * 16 + c]);
            mx = fmaxf(mx, __shfl_xor_sync(0xffffffffu, mx, 1));
            mx = fmaxf(mx, __shfl_xor_sync(0xffffffffu, mx, 2));
            float mold = mrow[r];
            float mnew = fmaxf(mold, mx);
            float sum = 0.f;
            #pragma unroll
            for (int c = 0; c < 16; c++) {
                float p = __expf(Ps[r * 65 + sub * 16 + c] - mnew);
                Ps[r * 65 + sub * 16 + c] = p;
                sum += p;
            }
            sum += __shfl_xor_sync(0xffffffffu, sum, 1);
            sum += __shfl_xor_sync(0xffffffffu, sum, 2);
            if (sub == 0) {
                float al = __expf(mold - mnew);
                mrow[r] = mnew;
                lrow[r] = lrow[r] * al + sum;
                arow[r] = al;
            }
        }
        __syncthreads();

        // rescale accumulators, then O += P @ V
        float al[4];
        #pragma unroll
        for (int i = 0; i < 4; i++) al[i] = arow[ty * 4 + i];
        #pragma unroll
        for (int i = 0; i < 4; i++)
            #pragma unroll
            for (int j = 0; j < 4; j++) o[i][j] *= al[i];

        for (int k = 0; k < 64; k++) {
            float pv[4], vv[4];
            #pragma unroll
            for (int i = 0; i < 4; i++) pv[i] = Ps[(ty * 4 + i) * 65 + k];
            #pragma unroll
            for (int j = 0; j < 4; j++) vv[j] = Vs[k * 64 + tx * 4 + j];
            #pragma unroll
            for (int i = 0; i < 4; i++)
                #pragma unroll
                for (int j = 0; j < 4; j++)
                    o[i][j] = fmaf(pv[i], vv[j], o[i][j]);
        }
        __syncthreads();
    }

    // write out: g_attn[(b*SEQ + qb + r) * CDIM + h*64 + c]
    #pragma unroll
    for (int i = 0; i < 4; i++) {
        int r = ty * 4 + i;
        float inv_l = 1.0f / lrow[r];
        size_t obase = (size_t)(b * SEQ + qb + r) * CDIM + h * HDIM + tx * 4;
        #pragma unroll
        for (int j = 0; j < 4; j++)
            outp[obase + j] = o[i][j] * inv_l;
    }
}

// ---------------------------------------------------------------------------
// Launch
// ---------------------------------------------------------------------------
extern "C" void kernel_launch(void* const* d_in, const int* in_sizes, int n_in,
                              void* d_out, int out_size)
{
    const float* x      = (const float*)d_in[0];
    const float* ln1_g  = (const float*)d_in[1];
    const float* ln1_b  = (const float*)d_in[2];
    const float* qkv_w  = (const float*)d_in[3];
    const float* qkv_b  = (const float*)d_in[4];
    const float* proj_w = (const float*)d_in[5];
    const float* proj_b = (const float*)d_in[6];
    const float* ln2_g  = (const float*)d_in[7];
    const float* ln2_b  = (const float*)d_in[8];
    const float* fc1_w  = (const float*)d_in[9];
    const float* fc1_b  = (const float*)d_in[10];
    const float* fc2_w  = (const float*)d_in[11];
    const float* fc2_b  = (const float*)d_in[12];
    float* out = (float*)d_out;

    float *p_xn1, *p_qkv, *p_attn, *p_x2, *p_hn, *p_h1;
    cudaGetSymbolAddress((void**)&p_xn1,  g_xn1);
    cudaGetSymbolAddress((void**)&p_qkv,  g_qkv);
    cudaGetSymbolAddress((void**)&p_attn, g_attn);
    cudaGetSymbolAddress((void**)&p_x2,   g_x2);
    cudaGetSymbolAddress((void**)&p_hn,   g_hn);
    cudaGetSymbolAddress((void**)&p_h1,   g_h1);

    cudaFuncSetAttribute(attn_kernel,
                         cudaFuncAttributeMaxDynamicSharedMemorySize,
                         ATTN_SMEM_BYTES);

    // 1) LN1
    ln_kernel<<<TOKENS, 256>>>(x, ln1_g, ln1_b, p_xn1);

    // 2) qkv = xn1 @ qkv_w + qkv_b     [16384,768]x[768,2304]
    {
        dim3 grid(C3 / 128, TOKENS / 128);
        sgemm128<false,false><<<grid, 256>>>(p_xn1, qkv_w, qkv_b, nullptr,
                                             p_qkv, TOKENS, C3, CDIM);
    }

    // 3) attention -> p_attn
    {
        dim3 grid(SEQ / 64, BATCH * NHEADS);
        attn_kernel<<<grid, 256, ATTN_SMEM_BYTES>>>(p_qkv, p_attn);
    }

    // 4) x2 = x + attn @ proj_w + proj_b
    {
        dim3 grid(CDIM / 128, TOKENS / 128);
        sgemm128<false,true><<<grid, 256>>>(p_attn, proj_w, proj_b, x,
                                            p_x2, TOKENS, CDIM, CDIM);
    }

    // 5) LN2
    ln_kernel<<<TOKENS, 256>>>(p_x2, ln2_g, ln2_b, p_hn);

    // 6) h1 = gelu(hn @ fc1_w + fc1_b)
    {
        dim3 grid(HID / 128, TOKENS / 128);
        sgemm128<true,false><<<grid, 256>>>(p_hn, fc1_w, fc1_b, nullptr,
                                            p_h1, TOKENS, HID, CDIM);
    }

    // 7) out = x2 + h1 @ fc2_w + fc2_b
    {
        dim3 grid(CDIM / 128, TOKENS / 128);
        sgemm128<false,true><<<grid, 256>>>(p_h1, fc2_w, fc2_b, p_x2,
                                            out, TOKENS, CDIM, HID);
    }
}

// round 2
// speedup vs baseline: 2.2010x; 2.2010x over previous
#include <cuda_runtime.h>
#include <cuda_bf16.h>
#include <math.h>

// Problem constants
#define BATCH   16
#define SEQ     1024
#define TOKENS  (BATCH*SEQ)     // 16384
#define CDIM    768
#define C3      (3*CDIM)        // 2304
#define HID     3072
#define NHEADS  12
#define HDIM    64
#define LN_EPS  1e-5f

// ---------------------------------------------------------------------------
// Scratch (device globals; allocation APIs are forbidden)
// ---------------------------------------------------------------------------
__device__ float g_xn1 [ (size_t)TOKENS * CDIM ];
__device__ float g_qkv [ (size_t)TOKENS * C3   ];
__device__ float g_attn[ (size_t)TOKENS * CDIM ];
__device__ float g_x2  [ (size_t)TOKENS * CDIM ];
__device__ float g_hn  [ (size_t)TOKENS * CDIM ];
__device__ float g_h1  [ (size_t)TOKENS * HID  ];

// ---------------------------------------------------------------------------
// LayerNorm: one block (256 thr) per row of 768
// ---------------------------------------------------------------------------
__global__ __launch_bounds__(256)
void ln_kernel(const float* __restrict__ x, const float* __restrict__ gam,
               const float* __restrict__ bet, float* __restrict__ out)
{
    int row = blockIdx.x;
    int tid = threadIdx.x;
    const float* xr = x + (size_t)row * CDIM;

    float v0 = xr[tid], v1 = xr[tid + 256], v2 = xr[tid + 512];

    __shared__ float red[8];
    __shared__ float mu_s, rs_s;

    float s = v0 + v1 + v2;
    #pragma unroll
    for (int off = 16; off > 0; off >>= 1) s += __shfl_xor_sync(0xffffffffu, s, off);
    if ((tid & 31) == 0) red[tid >> 5] = s;
    __syncthreads();
    if (tid == 0) {
        float t = 0.f;
        #pragma unroll
        for (int i = 0; i < 8; i++) t += red[i];
        mu_s = t * (1.0f / CDIM);
    }
    __syncthreads();
    float mu = mu_s;
    float d0 = v0 - mu, d1 = v1 - mu, d2 = v2 - mu;

    float q = d0*d0 + d1*d1 + d2*d2;
    #pragma unroll
    for (int off = 16; off > 0; off >>= 1) q += __shfl_xor_sync(0xffffffffu, q, off);
    __syncthreads();
    if ((tid & 31) == 0) red[tid >> 5] = q;
    __syncthreads();
    if (tid == 0) {
        float t = 0.f;
        #pragma unroll
        for (int i = 0; i < 8; i++) t += red[i];
        rs_s = rsqrtf(t * (1.0f / CDIM) + LN_EPS);
    }
    __syncthreads();
    float rs = rs_s;

    float* orow = out + (size_t)row * CDIM;
    orow[tid      ] = d0 * rs * gam[tid      ] + bet[tid      ];
    orow[tid + 256] = d1 * rs * gam[tid + 256] + bet[tid + 256];
    orow[tid + 512] = d2 * rs * gam[tid + 512] + bet[tid + 512];
}

// ---------------------------------------------------------------------------
// TF32 tensor-core GEMM: C[M,N] = A[M,K] @ B[K,N] + bias (+GELU) (+resid)
// 128x128x32 block tile, 8 warps (64x32 warp tiles), mma.m16n8k8.tf32,
// cp.async double buffering, conflict-free padded smem.
// M % 128 == 0, N % 128 == 0, K % 32 == 0 for all calls here.
// ---------------------------------------------------------------------------
#define BM 128
#define BN 128
#define BK 32
#define AS_STRIDE 36     // (4m + k) % 32 is a permutation -> conflict-free
#define BS_STRIDE 136    // (8k + n) % 32 is a permutation -> conflict-free
#define SMEM_A_FLOATS (BM * AS_STRIDE)   // 4608
#define SMEM_B_FLOATS (BK * BS_STRIDE)   // 4352
#define GEMM_SMEM_BYTES ((2 * SMEM_A_FLOATS + 2 * SMEM_B_FLOATS) * 4)  // 71680

__device__ __forceinline__ unsigned cvt_tf32(float x) {
    unsigned u;
    asm("cvt.rna.tf32.f32 %0, %1;" : "=r"(u) : "f"(x));
    return u;
}

__device__ __forceinline__ void mma_tf32(float* c, const unsigned* a, const unsigned* b) {
    asm volatile(
        "mma.sync.aligned.m16n8k8.row.col.f32.tf32.tf32.f32 "
        "{%0,%1,%2,%3}, {%4,%5,%6,%7}, {%8,%9}, {%0,%1,%2,%3};"
        : "+f"(c[0]), "+f"(c[1]), "+f"(c[2]), "+f"(c[3])
        : "r"(a[0]), "r"(a[1]), "r"(a[2]), "r"(a[3]), "r"(b[0]), "r"(b[1]));
}

__device__ __forceinline__ void cpasync16(void* smem_ptr, const void* gmem_ptr) {
    unsigned s = (unsigned)__cvta_generic_to_shared(smem_ptr);
    asm volatile("cp.async.cg.shared.global [%0], [%1], 16;" :: "r"(s), "l"(gmem_ptr));
}

template<bool DO_GELU, bool DO_RESID>
__global__ __launch_bounds__(256, 2)
void tgemm(const float* __restrict__ A, const float* __restrict__ B,
           const float* __restrict__ bias, const float* __restrict__ resid,
           float* __restrict__ C, int M, int N, int K)
{
    extern __shared__ float sm[];
    float* As = sm;                        // [2][BM][AS_STRIDE]
    float* Bs = sm + 2 * SMEM_A_FLOATS;    // [2][BK][BS_STRIDE]

    int tid  = threadIdx.x;
    int row0 = blockIdx.y * BM;
    int col0 = blockIdx.x * BN;
    int warp = tid >> 5;
    int lane = tid & 31;
    int wm   = (warp >> 2) * 64;   // warp m offset (0 or 64)
    int wn   = (warp & 3) * 32;    // warp n offset (0,32,64,96)
    int lr   = lane >> 2;          // 0..7
    int lc   = lane & 3;           // 0..3

    float acc[4][4][4];
    #pragma unroll
    for (int i = 0; i < 4; i++)
        #pragma unroll
        for (int j = 0; j < 4; j++)
            #pragma unroll
            for (int r = 0; r < 4; r++) acc[i][j][r] = 0.f;

    auto load_tiles = [&](int buf, int kt) {
        int k0 = kt * BK;
        const float* Ab = A + (size_t)row0 * K + k0;
        #pragma unroll
        for (int i = 0; i < 4; i++) {
            int idx = tid + i * 256;           // 0..1023
            int r   = idx >> 3;                // 0..127
            int c4  = (idx & 7) * 4;           // 0..28
            cpasync16(&As[buf * SMEM_A_FLOATS + r * AS_STRIDE + c4],
                      Ab + (size_t)r * K + c4);
        }
        const float* Bb = B + (size_t)k0 * N + col0;
        #pragma unroll
        for (int i = 0; i < 4; i++) {
            int idx = tid + i * 256;
            int r   = idx >> 5;                // 0..31
            int c4  = (idx & 31) * 4;          // 0..124
            cpasync16(&Bs[buf * SMEM_B_FLOATS + r * BS_STRIDE + c4],
                      Bb + (size_t)r * N + c4);
        }
        asm volatile("cp.async.commit_group;");
    };

    int KT = K / BK;
    load_tiles(0, 0);
    int buf = 0;

    for (int kt = 0; kt < KT; kt++) {
        if (kt + 1 < KT) {
            load_tiles(buf ^ 1, kt + 1);
            asm volatile("cp.async.wait_group 1;");
        } else {
            asm volatile("cp.async.wait_group 0;");
        }
        __syncthreads();

        const float* Ab = &As[buf * SMEM_A_FLOATS];
        const float* Bb = &Bs[buf * SMEM_B_FLOATS];

        #pragma unroll
        for (int ks = 0; ks < 4; ks++) {
            int k0 = ks * 8;
            unsigned af[4][4], bf[4][2];
            #pragma unroll
            for (int i = 0; i < 4; i++) {
                int mb = wm + i * 16;
                af[i][0] = cvt_tf32(Ab[(mb + lr    ) * AS_STRIDE + k0 + lc    ]);
                af[i][1] = cvt_tf32(Ab[(mb + lr + 8) * AS_STRIDE + k0 + lc    ]);
                af[i][2] = cvt_tf32(Ab[(mb + lr    ) * AS_STRIDE + k0 + lc + 4]);
                af[i][3] = cvt_tf32(Ab[(mb + lr + 8) * AS_STRIDE + k0 + lc + 4]);
            }
            #pragma unroll
            for (int j = 0; j < 4; j++) {
                int nb = wn + j * 8;
                bf[j][0] = cvt_tf32(Bb[(k0 + lc    ) * BS_STRIDE + nb + lr]);
                bf[j][1] = cvt_tf32(Bb[(k0 + 4 + lc) * BS_STRIDE + nb + lr]);
            }
            #pragma unroll
            for (int i = 0; i < 4; i++)
                #pragma unroll
                for (int j = 0; j < 4; j++)
                    mma_tf32(acc[i][j], af[i], bf[j]);
        }
        __syncthreads();
        buf ^= 1;
    }

    // Epilogue
    #pragma unroll
    for (int i = 0; i < 4; i++) {
        int r0 = row0 + wm + i * 16 + lr;
        #pragma unroll
        for (int j = 0; j < 4; j++) {
            int cc = col0 + wn + j * 8 + lc * 2;
            float2 bb = *(const float2*)&bias[cc];
            float v0 = acc[i][j][0] + bb.x;
            float v1 = acc[i][j][1] + bb.y;
            float v2 = acc[i][j][2] + bb.x;
            float v3 = acc[i][j][3] + bb.y;
            if (DO_GELU) {
                v0 = 0.5f * v0 * (1.0f + erff(v0 * 0.70710678118654752f));
                v1 = 0.5f * v1 * (1.0f + erff(v1 * 0.70710678118654752f));
                v2 = 0.5f * v2 * (1.0f + erff(v2 * 0.70710678118654752f));
                v3 = 0.5f * v3 * (1.0f + erff(v3 * 0.70710678118654752f));
            }
            size_t o0 = (size_t)r0 * N + cc;
            size_t o1 = (size_t)(r0 + 8) * N + cc;
            if (DO_RESID) {
                float2 ra = *(const float2*)&resid[o0];
                float2 rb = *(const float2*)&resid[o1];
                v0 += ra.x; v1 += ra.y; v2 += rb.x; v3 += rb.y;
            }
            *(float2*)&C[o0] = make_float2(v0, v1);
            *(float2*)&C[o1] = make_float2(v2, v3);
        }
    }
}

// ---------------------------------------------------------------------------
// Flash attention (fp32): one block per (64-query tile, b*h).
// ---------------------------------------------------------------------------
#define ATTN_SMEM_FLOATS (64*65 + 64*65 + 64*64 + 64*65 + 3*64)
#define ATTN_SMEM_BYTES  (ATTN_SMEM_FLOATS * 4)

__global__ __launch_bounds__(256)
void attn_kernel(const float* __restrict__ qkv, float* __restrict__ outp)
{
    extern __shared__ float smf[];
    float* Qt   = smf;
    float* Kt   = Qt + 64 * 65;
    float* Vs   = Kt + 64 * 65;
    float* Ps   = Vs + 64 * 64;
    float* mrow = Ps + 64 * 65;
    float* lrow = mrow + 64;
    float* arow = lrow + 64;

    int tid = threadIdx.x;
    int qb  = blockIdx.x * 64;
    int bh  = blockIdx.y;
    int b   = bh / NHEADS;
    int h   = bh % NHEADS;

    const float* base = qkv + (size_t)b * SEQ * C3 + h * HDIM;

    for (int idx = tid; idx < 4096; idx += 256) {
        int n = idx >> 6, d = idx & 63;
        Qt[d * 65 + n] = base[(size_t)(qb + n) * C3 + d];
    }
    if (tid < 64) { mrow[tid] = -1e30f; lrow[tid] = 0.f; }

    int ty = tid >> 4, tx = tid & 15;
    float o[4][4];
    #pragma unroll
    for (int i = 0; i < 4; i++)
        #pragma unroll
        for (int j = 0; j < 4; j++) o[i][j] = 0.f;

    __syncthreads();

    for (int kt = 0; kt < SEQ / 64; kt++) {
        int kb = kt * 64;
        for (int idx = tid; idx < 4096; idx += 256) {
            int n = idx >> 6, d = idx & 63;
            size_t roff = (size_t)(kb + n) * C3;
            Kt[d * 65 + n] = base[roff + CDIM + d];
            Vs[n * 64 + d] = base[roff + 2 * CDIM + d];
        }
        __syncthreads();

        float s[4][4];
        #pragma unroll
        for (int i = 0; i < 4; i++)
            #pragma unroll
            for (int j = 0; j < 4; j++) s[i][j] = 0.f;

        for (int k = 0; k < 64; k++) {
            float qv[4], kv[4];
            #pragma unroll
            for (int i = 0; i < 4; i++) qv[i] = Qt[k * 65 + ty * 4 + i];
            #pragma unroll
            for (int j = 0; j < 4; j++) kv[j] = Kt[k * 65 + tx * 4 + j];
            #pragma unroll
            for (int i = 0; i < 4; i++)
                #pragma unroll
                for (int j = 0; j < 4; j++)
                    s[i][j] = fmaf(qv[i], kv[j], s[i][j]);
        }
        #pragma unroll
        for (int i = 0; i < 4; i++)
            #pragma unroll
            for (int j = 0; j < 4; j++)
                Ps[(ty * 4 + i) * 65 + tx * 4 + j] = s[i][j] * 0.125f;
        __syncthreads();

        {
            int r = tid >> 2, sub = tid & 3;
            float mx = -1e30f;
            #pragma unroll
            for (int c = 0; c < 16; c++)
                mx = fmaxf(mx, Ps[r * 65 + sub * 16 + c]);
            mx = fmaxf(mx, __shfl_xor_sync(0xffffffffu, mx, 1));
            mx = fmaxf(mx, __shfl_xor_sync(0xffffffffu, mx, 2));
            float mold = mrow[r];
            float mnew = fmaxf(mold, mx);
            float sum = 0.f;
            #pragma unroll
            for (int c = 0; c < 16; c++) {
                float p = __expf(Ps[r * 65 + sub * 16 + c] - mnew);
                Ps[r * 65 + sub * 16 + c] = p;
                sum += p;
            }
            sum += __shfl_xor_sync(0xffffffffu, sum, 1);
            sum += __shfl_xor_sync(0xffffffffu, sum, 2);
            if (sub == 0) {
                float al = __expf(mold - mnew);
                mrow[r] = mnew;
                lrow[r] = lrow[r] * al + sum;
                arow[r] = al;
            }
        }
        __syncthreads();

        float al[4];
        #pragma unroll
        for (int i = 0; i < 4; i++) al[i] = arow[ty * 4 + i];
        #pragma unroll
        for (int i = 0; i < 4; i++)
            #pragma unroll
            for (int j = 0; j < 4; j++) o[i][j] *= al[i];

        for (int k = 0; k < 64; k++) {
            float pv[4], vv[4];
            #pragma unroll
            for (int i = 0; i < 4; i++) pv[i] = Ps[(ty * 4 + i) * 65 + k];
            #pragma unroll
            for (int j = 0; j < 4; j++) vv[j] = Vs[k * 64 + tx * 4 + j];
            #pragma unroll
            for (int i = 0; i < 4; i++)
                #pragma unroll
                for (int j = 0; j < 4; j++)
                    o[i][j] = fmaf(pv[i], vv[j], o[i][j]);
        }
        __syncthreads();
    }

    #pragma unroll
    for (int i = 0; i < 4; i++) {
        int r = ty * 4 + i;
        float inv_l = 1.0f / lrow[r];
        size_t obase = (size_t)(b * SEQ + qb + r) * CDIM + h * HDIM + tx * 4;
        #pragma unroll
        for (int j = 0; j < 4; j++)
            outp[obase + j] = o[i][j] * inv_l;
    }
}

// ---------------------------------------------------------------------------
// Launch
// ---------------------------------------------------------------------------
extern "C" void kernel_launch(void* const* d_in, const int* in_sizes, int n_in,
                              void* d_out, int out_size)
{
    const float* x      = (const float*)d_in[0];
    const float* ln1_g  = (const float*)d_in[1];
    const float* ln1_b  = (const float*)d_in[2];
    const float* qkv_w  = (const float*)d_in[3];
    const float* qkv_b  = (const float*)d_in[4];
    const float* proj_w = (const float*)d_in[5];
    const float* proj_b = (const float*)d_in[6];
    const float* ln2_g  = (const float*)d_in[7];
    const float* ln2_b  = (const float*)d_in[8];
    const float* fc1_w  = (const float*)d_in[9];
    const float* fc1_b  = (const float*)d_in[10];
    const float* fc2_w  = (const float*)d_in[11];
    const float* fc2_b  = (const float*)d_in[12];
    float* out = (float*)d_out;

    float *p_xn1, *p_qkv, *p_attn, *p_x2, *p_hn, *p_h1;
    cudaGetSymbolAddress((void**)&p_xn1,  g_xn1);
    cudaGetSymbolAddress((void**)&p_qkv,  g_qkv);
    cudaGetSymbolAddress((void**)&p_attn, g_attn);
    cudaGetSymbolAddress((void**)&p_x2,   g_x2);
    cudaGetSymbolAddress((void**)&p_hn,   g_hn);
    cudaGetSymbolAddress((void**)&p_h1,   g_h1);

    cudaFuncSetAttribute(attn_kernel,
                         cudaFuncAttributeMaxDynamicSharedMemorySize,
                         ATTN_SMEM_BYTES);
    cudaFuncSetAttribute(tgemm<false,false>,
                         cudaFuncAttributeMaxDynamicSharedMemorySize,
                         GEMM_SMEM_BYTES);
    cudaFuncSetAttribute(tgemm<false,true>,
                         cudaFuncAttributeMaxDynamicSharedMemorySize,
                         GEMM_SMEM_BYTES);
    cudaFuncSetAttribute(tgemm<true,false>,
                         cudaFuncAttributeMaxDynamicSharedMemorySize,
                         GEMM_SMEM_BYTES);

    // 1) LN1
    ln_kernel<<<TOKENS, 256>>>(x, ln1_g, ln1_b, p_xn1);

    // 2) qkv = xn1 @ qkv_w + qkv_b
    {
        dim3 grid(C3 / BN, TOKENS / BM);
        tgemm<false,false><<<grid, 256, GEMM_SMEM_BYTES>>>(
            p_xn1, qkv_w, qkv_b, nullptr, p_qkv, TOKENS, C3, CDIM);
    }

    // 3) attention
    {
        dim3 grid(SEQ / 64, BATCH * NHEADS);
        attn_kernel<<<grid, 256, ATTN_SMEM_BYTES>>>(p_qkv, p_attn);
    }

    // 4) x2 = x + attn @ proj_w + proj_b
    {
        dim3 grid(CDIM / BN, TOKENS / BM);
        tgemm<false,true><<<grid, 256, GEMM_SMEM_BYTES>>>(
            p_attn, proj_w, proj_b, x, p_x2, TOKENS, CDIM, CDIM);
    }

    // 5) LN2
    ln_kernel<<<TOKENS, 256>>>(p_x2, ln2_g, ln2_b, p_hn);

    // 6) h1 = gelu(hn @ fc1_w + fc1_b)
    {
        dim3 grid(HID / BN, TOKENS / BM);
        tgemm<true,false><<<grid, 256, GEMM_SMEM_BYTES>>>(
            p_hn, fc1_w, fc1_b, nullptr, p_h1, TOKENS, HID, CDIM);
    }

    // 7) out = x2 + h1 @ fc2_w + fc2_b
    {
        dim3 grid(CDIM / BN, TOKENS / BM);
        tgemm<false,true><<<grid, 256, GEMM_SMEM_BYTES>>>(
            p_h1, fc2_w, fc2_b, p_x2, out, TOKENS, CDIM, HID);
    }
}

// round 3
// speedup vs baseline: 3.5385x; 1.6076x over previous
#include <cuda_runtime.h>
#include <cuda_bf16.h>
#include <math.h>

// Problem constants
#define BATCH   16
#define SEQ     1024
#define TOKENS  (BATCH*SEQ)     // 16384
#define CDIM    768
#define C3      (3*CDIM)        // 2304
#define HID     3072
#define NHEADS  12
#define HDIM    64
#define LN_EPS  1e-5f

// ---------------------------------------------------------------------------
// Scratch (device globals; allocation APIs are forbidden)
// ---------------------------------------------------------------------------
__device__ float g_xn1 [ (size_t)TOKENS * CDIM ];
__device__ float g_qkv [ (size_t)TOKENS * C3   ];
__device__ float g_attn[ (size_t)TOKENS * CDIM ];
__device__ float g_x2  [ (size_t)TOKENS * CDIM ];
__device__ float g_hn  [ (size_t)TOKENS * CDIM ];
__device__ float g_h1  [ (size_t)TOKENS * HID  ];
// TF32-rounded weights
__device__ float g_wq  [ (size_t)CDIM * C3  ];
__device__ float g_wp  [ (size_t)CDIM * CDIM];
__device__ float g_w1  [ (size_t)CDIM * HID ];
__device__ float g_w2  [ (size_t)HID  * CDIM];

// ---------------------------------------------------------------------------
// Helpers
// ---------------------------------------------------------------------------
__device__ __forceinline__ float rtf(float x) {
    float y;
    asm("cvt.rna.tf32.f32 %0, %1;" : "=f"(y) : "f"(x));
    return y;
}
__device__ __forceinline__ float ex2f(float x) {
    float y;
    asm("ex2.approx.f32 %0, %1;" : "=f"(y) : "f"(x));
    return y;
}
__device__ __forceinline__ void mma_tf32(float* c, const unsigned* a, const unsigned* b) {
    asm volatile(
        "mma.sync.aligned.m16n8k8.row.col.f32.tf32.tf32.f32 "
        "{%0,%1,%2,%3}, {%4,%5,%6,%7}, {%8,%9}, {%0,%1,%2,%3};"
        : "+f"(c[0]), "+f"(c[1]), "+f"(c[2]), "+f"(c[3])
        : "r"(a[0]), "r"(a[1]), "r"(a[2]), "r"(a[3]), "r"(b[0]), "r"(b[1]));
}
__device__ __forceinline__ void cpasync16(void* smem_ptr, const void* gmem_ptr) {
    unsigned s = (unsigned)__cvta_generic_to_shared(smem_ptr);
    asm volatile("cp.async.cg.shared.global [%0], [%1], 16;" :: "r"(s), "l"(gmem_ptr));
}

// ---------------------------------------------------------------------------
// Weight pre-rounding to TF32 (RNA): runs inside the graph, ~idempotent.
// ---------------------------------------------------------------------------
__global__ __launch_bounds__(256)
void round_w_kernel(const float4* __restrict__ in, float4* __restrict__ out, int n4)
{
    int i = blockIdx.x * 256 + threadIdx.x;
    if (i < n4) {
        float4 v = in[i];
        v.x = rtf(v.x); v.y = rtf(v.y); v.z = rtf(v.z); v.w = rtf(v.w);
        out[i] = v;
    }
}

// ---------------------------------------------------------------------------
// LayerNorm (output rounded to TF32 — it is only consumed as a GEMM A operand)
// ---------------------------------------------------------------------------
__global__ __launch_bounds__(256)
void ln_kernel(const float* __restrict__ x, const float* __restrict__ gam,
               const float* __restrict__ bet, float* __restrict__ out)
{
    int row = blockIdx.x;
    int tid = threadIdx.x;
    const float* xr = x + (size_t)row * CDIM;

    float v0 = xr[tid], v1 = xr[tid + 256], v2 = xr[tid + 512];

    __shared__ float red[8];
    __shared__ float mu_s, rs_s;

    float s = v0 + v1 + v2;
    #pragma unroll
    for (int off = 16; off > 0; off >>= 1) s += __shfl_xor_sync(0xffffffffu, s, off);
    if ((tid & 31) == 0) red[tid >> 5] = s;
    __syncthreads();
    if (tid == 0) {
        float t = 0.f;
        #pragma unroll
        for (int i = 0; i < 8; i++) t += red[i];
        mu_s = t * (1.0f / CDIM);
    }
    __syncthreads();
    float mu = mu_s;
    float d0 = v0 - mu, d1 = v1 - mu, d2 = v2 - mu;

    float q = d0*d0 + d1*d1 + d2*d2;
    #pragma unroll
    for (int off = 16; off > 0; off >>= 1) q += __shfl_xor_sync(0xffffffffu, q, off);
    __syncthreads();
    if ((tid & 31) == 0) red[tid >> 5] = q;
    __syncthreads();
    if (tid == 0) {
        float t = 0.f;
        #pragma unroll
        for (int i = 0; i < 8; i++) t += red[i];
        rs_s = rsqrtf(t * (1.0f / CDIM) + LN_EPS);
    }
    __syncthreads();
    float rs = rs_s;

    float* orow = out + (size_t)row * CDIM;
    orow[tid      ] = rtf(d0 * rs * gam[tid      ] + bet[tid      ]);
    orow[tid + 256] = rtf(d1 * rs * gam[tid + 256] + bet[tid + 256]);
    orow[tid + 512] = rtf(d2 * rs * gam[tid + 512] + bet[tid + 512]);
}

// ---------------------------------------------------------------------------
// TF32 tensor-core GEMM (operands are pre-rounded; no cvt in the hot loop).
// 128x128x32 tile, 8 warps, mma.m16n8k8, cp.async double buffering.
// ---------------------------------------------------------------------------
#define BM 128
#define BN 128
#define BK 32
#define AS_STRIDE 36
#define BS_STRIDE 136
#define SMEM_A_FLOATS (BM * AS_STRIDE)
#define SMEM_B_FLOATS (BK * BS_STRIDE)
#define GEMM_SMEM_BYTES ((2 * SMEM_A_FLOATS + 2 * SMEM_B_FLOATS) * 4)

template<bool DO_GELU, bool DO_RESID, bool ROUND_OUT>
__global__ __launch_bounds__(256, 2)
void tgemm(const float* __restrict__ A, const float* __restrict__ B,
           const float* __restrict__ bias, const float* __restrict__ resid,
           float* __restrict__ C, int M, int N, int K)
{
    extern __shared__ float sm[];
    float* As = sm;
    float* Bs = sm + 2 * SMEM_A_FLOATS;

    int tid  = threadIdx.x;
    int row0 = blockIdx.y * BM;
    int col0 = blockIdx.x * BN;
    int warp = tid >> 5;
    int lane = tid & 31;
    int wm   = (warp >> 2) * 64;
    int wn   = (warp & 3) * 32;
    int lr   = lane >> 2;
    int lc   = lane & 3;

    float acc[4][4][4];
    #pragma unroll
    for (int i = 0; i < 4; i++)
        #pragma unroll
        for (int j = 0; j < 4; j++)
            #pragma unroll
            for (int r = 0; r < 4; r++) acc[i][j][r] = 0.f;

    auto load_tiles = [&](int buf, int kt) {
        int k0 = kt * BK;
        const float* Ab = A + (size_t)row0 * K + k0;
        #pragma unroll
        for (int i = 0; i < 4; i++) {
            int idx = tid + i * 256;
            int r   = idx >> 3;
            int c4  = (idx & 7) * 4;
            cpasync16(&As[buf * SMEM_A_FLOATS + r * AS_STRIDE + c4],
                      Ab + (size_t)r * K + c4);
        }
        const float* Bb = B + (size_t)k0 * N + col0;
        #pragma unroll
        for (int i = 0; i < 4; i++) {
            int idx = tid + i * 256;
            int r   = idx >> 5;
            int c4  = (idx & 31) * 4;
            cpasync16(&Bs[buf * SMEM_B_FLOATS + r * BS_STRIDE + c4],
                      Bb + (size_t)r * N + c4);
        }
        asm volatile("cp.async.commit_group;");
    };

    int KT = K / BK;
    load_tiles(0, 0);
    int buf = 0;

    for (int kt = 0; kt < KT; kt++) {
        if (kt + 1 < KT) {
            load_tiles(buf ^ 1, kt + 1);
            asm volatile("cp.async.wait_group 1;");
        } else {
            asm volatile("cp.async.wait_group 0;");
        }
        __syncthreads();

        const float* Ab = &As[buf * SMEM_A_FLOATS];
        const float* Bb = &Bs[buf * SMEM_B_FLOATS];

        #pragma unroll
        for (int ks = 0; ks < 4; ks++) {
            int k0 = ks * 8;
            unsigned af[4][4], bf[4][2];
            #pragma unroll
            for (int i = 0; i < 4; i++) {
                int mb = wm + i * 16;
                af[i][0] = __float_as_uint(Ab[(mb + lr    ) * AS_STRIDE + k0 + lc    ]);
                af[i][1] = __float_as_uint(Ab[(mb + lr + 8) * AS_STRIDE + k0 + lc    ]);
                af[i][2] = __float_as_uint(Ab[(mb + lr    ) * AS_STRIDE + k0 + lc + 4]);
                af[i][3] = __float_as_uint(Ab[(mb + lr + 8) * AS_STRIDE + k0 + lc + 4]);
            }
            #pragma unroll
            for (int j = 0; j < 4; j++) {
                int nb = wn + j * 8;
                bf[j][0] = __float_as_uint(Bb[(k0 + lc    ) * BS_STRIDE + nb + lr]);
                bf[j][1] = __float_as_uint(Bb[(k0 + 4 + lc) * BS_STRIDE + nb + lr]);
            }
            #pragma unroll
            for (int i = 0; i < 4; i++)
                #pragma unroll
                for (int j = 0; j < 4; j++)
                    mma_tf32(acc[i][j], af[i], bf[j]);
        }
        __syncthreads();
        buf ^= 1;
    }

    #pragma unroll
    for (int i = 0; i < 4; i++) {
        int r0 = row0 + wm + i * 16 + lr;
        #pragma unroll
        for (int j = 0; j < 4; j++) {
            int cc = col0 + wn + j * 8 + lc * 2;
            float2 bb = *(const float2*)&bias[cc];
            float v0 = acc[i][j][0] + bb.x;
            float v1 = acc[i][j][1] + bb.y;
            float v2 = acc[i][j][2] + bb.x;
            float v3 = acc[i][j][3] + bb.y;
            if (DO_GELU) {
                v0 = 0.5f * v0 * (1.0f + erff(v0 * 0.70710678118654752f));
                v1 = 0.5f * v1 * (1.0f + erff(v1 * 0.70710678118654752f));
                v2 = 0.5f * v2 * (1.0f + erff(v2 * 0.70710678118654752f));
                v3 = 0.5f * v3 * (1.0f + erff(v3 * 0.70710678118654752f));
            }
            size_t o0 = (size_t)r0 * N + cc;
            size_t o1 = (size_t)(r0 + 8) * N + cc;
            if (DO_RESID) {
                float2 ra = *(const float2*)&resid[o0];
                float2 rb = *(const float2*)&resid[o1];
                v0 += ra.x; v1 += ra.y; v2 += rb.x; v3 += rb.y;
            }
            if (ROUND_OUT) {
                v0 = rtf(v0); v1 = rtf(v1); v2 = rtf(v2); v3 = rtf(v3);
            }
            *(float2*)&C[o0] = make_float2(v0, v1);
            *(float2*)&C[o1] = make_float2(v2, v3);
        }
    }
}

// ---------------------------------------------------------------------------
// Tensor-core flash attention.
// Block = 64 queries x 1 head, 4 warps (16 q-rows each), key tiles of 64.
// Q frags hoisted in regs; K,V natural [key][d] smem; register softmax.
// log2e folded into Q scale so softmax uses ex2 directly.
// ---------------------------------------------------------------------------
#define AST   68    // stride for Qs/Ks/Ps
#define VST   72    // stride for Vs (conflict-free B-frag loads)
#define ATTN_SMEM ((3*64*AST + 64*VST) * 4)   // 70656 B

__global__ __launch_bounds__(128)
void attn_tc(const float* __restrict__ qkv, float* __restrict__ outp)
{
    extern __shared__ float smf[];
    float* Qs = smf;
    float* Ks = smf + 64 * AST;
    float* Ps = smf + 2 * 64 * AST;
    float* Vs = smf + 3 * 64 * AST;

    int tid  = threadIdx.x;
    int warp = tid >> 5;
    int lane = tid & 31;
    int lr   = lane >> 2;
    int lc   = lane & 3;
    int qb   = blockIdx.x * 64;
    int b    = blockIdx.y / NHEADS;
    int h    = blockIdx.y % NHEADS;
    const float* base = qkv + (size_t)b * SEQ * C3 + h * HDIM;

    const float QS = 0.125f * 1.4426950408889634f;  // scale * log2(e)

    // Load Q tile (scaled + rounded)
    for (int idx = tid; idx < 1024; idx += 128) {
        int r = idx >> 4, c4 = (idx & 15) << 2;
        float4 v = *(const float4*)&base[(size_t)(qb + r) * C3 + c4];
        v.x = rtf(v.x * QS); v.y = rtf(v.y * QS);
        v.z = rtf(v.z * QS); v.w = rtf(v.w * QS);
        *(float4*)&Qs[r * AST + c4] = v;
    }
    __syncthreads();

    // Hoist Q fragments for all 8 k-steps
    unsigned qf[8][4];
    #pragma unroll
    for (int ks = 0; ks < 8; ks++) {
        const float* qp = &Qs[(16 * warp + lr) * AST + ks * 8 + lc];
        qf[ks][0] = __float_as_uint(qp[0]);
        qf[ks][1] = __float_as_uint(qp[8 * AST]);
        qf[ks][2] = __float_as_uint(qp[4]);
        qf[ks][3] = __float_as_uint(qp[8 * AST + 4]);
    }

    float m1 = -1e30f, m2 = -1e30f, l1 = 0.f, l2 = 0.f;
    float oc[8][4];
    #pragma unroll
    for (int j = 0; j < 8; j++)
        #pragma unroll
        for (int r = 0; r < 4; r++) oc[j][r] = 0.f;

    for (int kt = 0; kt < SEQ / 64; kt++) {
        __syncthreads();   // all warps done reading Ks/Vs of previous tile
        for (int idx = tid; idx < 1024; idx += 128) {
            int r = idx >> 4, c4 = (idx & 15) << 2;
            size_t g = (size_t)(kt * 64 + r) * C3 + c4;
            float4 kv = *(const float4*)&base[g + CDIM];
            float4 vv = *(const float4*)&base[g + 2 * CDIM];
            kv.x = rtf(kv.x); kv.y = rtf(kv.y); kv.z = rtf(kv.z); kv.w = rtf(kv.w);
            vv.x = rtf(vv.x); vv.y = rtf(vv.y); vv.z = rtf(vv.z); vv.w = rtf(vv.w);
            *(float4*)&Ks[r * AST + c4] = kv;
            *(float4*)&Vs[r * VST + c4] = vv;
        }
        __syncthreads();

        // S (in log2 domain) = Qs @ Ks^T
        float sc[8][4];
        #pragma unroll
        for (int j = 0; j < 8; j++)
            #pragma unroll
            for (int r = 0; r < 4; r++) sc[j][r] = 0.f;

        #pragma unroll
        for (int ks = 0; ks < 8; ks++) {
            int k0 = ks * 8;
            unsigned kf[8][2];
            #pragma unroll
            for (int j = 0; j < 8; j++) {
                const float* kp = &Ks[(8 * j + lr) * AST + k0 + lc];
                kf[j][0] = __float_as_uint(kp[0]);
                kf[j][1] = __float_as_uint(kp[4]);
            }
            #pragma unroll
            for (int j = 0; j < 8; j++)
                mma_tf32(sc[j], qf[ks], kf[j]);
        }

        // Online softmax (rows lr and lr+8 of this warp's 16)
        float mx1 = -1e30f, mx2 = -1e30f;
        #pragma unroll
        for (int j = 0; j < 8; j++) {
            mx1 = fmaxf(mx1, fmaxf(sc[j][0], sc[j][1]));
            mx2 = fmaxf(mx2, fmaxf(sc[j][2], sc[j][3]));
        }
        mx1 = fmaxf(mx1, __shfl_xor_sync(0xffffffffu, mx1, 1));
        mx1 = fmaxf(mx1, __shfl_xor_sync(0xffffffffu, mx1, 2));
        mx2 = fmaxf(mx2, __shfl_xor_sync(0xffffffffu, mx2, 1));
        mx2 = fmaxf(mx2, __shfl_xor_sync(0xffffffffu, mx2, 2));

        float nm1 = fmaxf(m1, mx1), nm2 = fmaxf(m2, mx2);
        float a1 = ex2f(m1 - nm1), a2 = ex2f(m2 - nm2);
        float s1 = 0.f, s2 = 0.f;

        float* pr1 = &Ps[(16 * warp + lr) * AST + 2 * lc];
        float* pr2 = pr1 + 8 * AST;
        #pragma unroll
        for (int j = 0; j < 8; j++) {
            float p0 = ex2f(sc[j][0] - nm1);
            float p1 = ex2f(sc[j][1] - nm1);
            float p2 = ex2f(sc[j][2] - nm2);
            float p3 = ex2f(sc[j][3] - nm2);
            s1 += p0 + p1; s2 += p2 + p3;
            *(float2*)&pr1[8 * j] = make_float2(rtf(p0), rtf(p1));
            *(float2*)&pr2[8 * j] = make_float2(rtf(p2), rtf(p3));
        }
        s1 += __shfl_xor_sync(0xffffffffu, s1, 1);
        s1 += __shfl_xor_sync(0xffffffffu, s1, 2);
        s2 += __shfl_xor_sync(0xffffffffu, s2, 1);
        s2 += __shfl_xor_sync(0xffffffffu, s2, 2);
        l1 = l1 * a1 + s1;  l2 = l2 * a2 + s2;
        m1 = nm1;           m2 = nm2;
        #pragma unroll
        for (int j = 0; j < 8; j++) {
            oc[j][0] *= a1; oc[j][1] *= a1;
            oc[j][2] *= a2; oc[j][3] *= a2;
        }
        __syncwarp();

        // O += P @ V
        #pragma unroll
        for (int ks = 0; ks < 8; ks++) {
            int k0 = ks * 8;
            unsigned pf[4];
            const float* pp = &Ps[(16 * warp + lr) * AST + k0 + lc];
            pf[0] = __float_as_uint(pp[0]);
            pf[1] = __float_as_uint(pp[8 * AST]);
            pf[2] = __float_as_uint(pp[4]);
            pf[3] = __float_as_uint(pp[8 * AST + 4]);
            unsigned vf[8][2];
            #pragma unroll
            for (int j = 0; j < 8; j++) {
                vf[j][0] = __float_as_uint(Vs[(k0 + lc    ) * VST + 8 * j + lr]);
                vf[j][1] = __float_as_uint(Vs[(k0 + lc + 4) * VST + 8 * j + lr]);
            }
            #pragma unroll
            for (int j = 0; j < 8; j++)
                mma_tf32(oc[j], pf, vf[j]);
        }
    }

    // Epilogue: normalize, round (feeds proj GEMM A), write
    float il1 = 1.0f / l1, il2 = 1.0f / l2;
    int r1 = qb + 16 * warp + lr;
    #pragma unroll
    for (int j = 0; j < 8; j++) {
        int cc = h * HDIM + 8 * j + 2 * lc;
        size_t o0 = (size_t)(b * SEQ + r1) * CDIM + cc;
        size_t o1 = o0 + (size_t)8 * CDIM;
        *(float2*)&outp[o0] = make_float2(rtf(oc[j][0] * il1), rtf(oc[j][1] * il1));
        *(float2*)&outp[o1] = make_float2(rtf(oc[j][2] * il2), rtf(oc[j][3] * il2));
    }
}

// ---------------------------------------------------------------------------
// Launch
// ---------------------------------------------------------------------------
extern "C" void kernel_launch(void* const* d_in, const int* in_sizes, int n_in,
                              void* d_out, int out_size)
{
    const float* x      = (const float*)d_in[0];
    const float* ln1_g  = (const float*)d_in[1];
    const float* ln1_b  = (const float*)d_in[2];
    const float* qkv_w  = (const float*)d_in[3];
    const float* qkv_b  = (const float*)d_in[4];
    const float* proj_w = (const float*)d_in[5];
    const float* proj_b = (const float*)d_in[6];
    const float* ln2_g  = (const float*)d_in[7];
    const float* ln2_b  = (const float*)d_in[8];
    const float* fc1_w  = (const float*)d_in[9];
    const float* fc1_b  = (const float*)d_in[10];
    const float* fc2_w  = (const float*)d_in[11];
    const float* fc2_b  = (const float*)d_in[12];
    float* out = (float*)d_out;

    float *p_xn1, *p_qkv, *p_attn, *p_x2, *p_hn, *p_h1;
    float *p_wq, *p_wp, *p_w1, *p_w2;
    cudaGetSymbolAddress((void**)&p_xn1,  g_xn1);
    cudaGetSymbolAddress((void**)&p_qkv,  g_qkv);
    cudaGetSymbolAddress((void**)&p_attn, g_attn);
    cudaGetSymbolAddress((void**)&p_x2,   g_x2);
    cudaGetSymbolAddress((void**)&p_hn,   g_hn);
    cudaGetSymbolAddress((void**)&p_h1,   g_h1);
    cudaGetSymbolAddress((void**)&p_wq,   g_wq);
    cudaGetSymbolAddress((void**)&p_wp,   g_wp);
    cudaGetSymbolAddress((void**)&p_w1,   g_w1);
    cudaGetSymbolAddress((void**)&p_w2,   g_w2);

    cudaFuncSetAttribute(attn_tc,
                         cudaFuncAttributeMaxDynamicSharedMemorySize, ATTN_SMEM);
    cudaFuncSetAttribute(tgemm<false,false,false>,
                         cudaFuncAttributeMaxDynamicSharedMemorySize, GEMM_SMEM_BYTES);
    cudaFuncSetAttribute(tgemm<false,true,false>,
                         cudaFuncAttributeMaxDynamicSharedMemorySize, GEMM_SMEM_BYTES);
    cudaFuncSetAttribute(tgemm<true,false,true>,
                         cudaFuncAttributeMaxDynamicSharedMemorySize, GEMM_SMEM_BYTES);

    // 0) Round weights to TF32 once per replay
    {
        int n;
        n = CDIM * C3 / 4;
        round_w_kernel<<<(n + 255) / 256, 256>>>((const float4*)qkv_w, (float4*)p_wq, n);
        n = CDIM * CDIM / 4;
        round_w_kernel<<<(n + 255) / 256, 256>>>((const float4*)proj_w, (float4*)p_wp, n);
        n = CDIM * HID / 4;
        round_w_kernel<<<(n + 255) / 256, 256>>>((const float4*)fc1_w, (float4*)p_w1, n);
        n = HID * CDIM / 4;
        round_w_kernel<<<(n + 255) / 256, 256>>>((const float4*)fc2_w, (float4*)p_w2, n);
    }

    // 1) LN1 (rounded output)
    ln_kernel<<<TOKENS, 256>>>(x, ln1_g, ln1_b, p_xn1);

    // 2) qkv = xn1 @ wq + qkv_b
    {
        dim3 grid(C3 / BN, TOKENS / BM);
        tgemm<false,false,false><<<grid, 256, GEMM_SMEM_BYTES>>>(
            p_xn1, p_wq, qkv_b, nullptr, p_qkv, TOKENS, C3, CDIM);
    }

    // 3) attention (tensor cores, rounded output)
    {
        dim3 grid(SEQ / 64, BATCH * NHEADS);
        attn_tc<<<grid, 128, ATTN_SMEM>>>(p_qkv, p_attn);
    }

    // 4) x2 = x + attn @ wp + proj_b
    {
        dim3 grid(CDIM / BN, TOKENS / BM);
        tgemm<false,true,false><<<grid, 256, GEMM_SMEM_BYTES>>>(
            p_attn, p_wp, proj_b, x, p_x2, TOKENS, CDIM, CDIM);
    }

    // 5) LN2 (rounded output)
    ln_kernel<<<TOKENS, 256>>>(p_x2, ln2_g, ln2_b, p_hn);

    // 6) h1 = gelu(hn @ w1 + fc1_b), rounded
    {
        dim3 grid(HID / BN, TOKENS / BM);
        tgemm<true,false,true><<<grid, 256, GEMM_SMEM_BYTES>>>(
            p_hn, p_w1, fc1_b, nullptr, p_h1, TOKENS, HID, CDIM);
    }

    // 7) out = x2 + h1 @ w2 + fc2_b
    {
        dim3 grid(CDIM / BN, TOKENS / BM);
        tgemm<false,true,false><<<grid, 256, GEMM_SMEM_BYTES>>>(
            p_h1, p_w2, fc2_b, p_x2, out, TOKENS, CDIM, HID);
    }
}

// round 5
// speedup vs baseline: 5.9853x; 1.6915x over previous
#include <cuda_runtime.h>
#include <cuda_fp16.h>
#include <math.h>
#include <stdint.h>

// Problem constants
#define BATCH   16
#define SEQ     1024
#define TOKENS  (BATCH*SEQ)     // 16384
#define CDIM    768
#define C3      (3*CDIM)        // 2304
#define HID     3072
#define NHEADS  12
#define HDIM    64
#define LN_EPS  1e-5f

// ---------------------------------------------------------------------------
// Scratch (device globals; allocation APIs are forbidden)
// ---------------------------------------------------------------------------
__device__ __half g_xn1 [ (size_t)TOKENS * CDIM ];   // LN1 out (half)
__device__ __half g_qkv [ (size_t)TOKENS * C3   ];   // qkv (half)
__device__ __half g_attn[ (size_t)TOKENS * CDIM ];   // attention out (half)
__device__ float  g_x2  [ (size_t)TOKENS * CDIM ];   // residual trunk (fp32)
__device__ __half g_hn  [ (size_t)TOKENS * CDIM ];   // LN2 out (half)
__device__ __half g_h1  [ (size_t)TOKENS * HID  ];   // gelu(fc1) (half)
// fp16, TRANSPOSED weights: wT[n][k]
__device__ __half g_wq  [ (size_t)C3   * CDIM ];
__device__ __half g_wp  [ (size_t)CDIM * CDIM ];
__device__ __half g_w1  [ (size_t)HID  * CDIM ];
__device__ __half g_w2  [ (size_t)CDIM * HID  ];

// ---------------------------------------------------------------------------
// Helpers
// ---------------------------------------------------------------------------
__device__ __forceinline__ float ex2f(float x) {
    float y;
    asm("ex2.approx.f32 %0, %1;" : "=f"(y) : "f"(x));
    return y;
}
__device__ __forceinline__ void mma_f16(float* c, const uint32_t* a, const uint32_t* b) {
    asm volatile(
        "mma.sync.aligned.m16n8k16.row.col.f32.f16.f16.f32 "
        "{%0,%1,%2,%3}, {%4,%5,%6,%7}, {%8,%9}, {%0,%1,%2,%3};"
        : "+f"(c[0]), "+f"(c[1]), "+f"(c[2]), "+f"(c[3])
        : "r"(a[0]), "r"(a[1]), "r"(a[2]), "r"(a[3]), "r"(b[0]), "r"(b[1]));
}
__device__ __forceinline__ void cpasync16(void* smem_ptr, const void* gmem_ptr) {
    uint32_t s = (uint32_t)__cvta_generic_to_shared(smem_ptr);
    asm volatile("cp.async.cg.shared.global [%0], [%1], 16;" :: "r"(s), "l"(gmem_ptr));
}
__device__ __forceinline__ uint32_t h2pack(float lo, float hi) {
    __half2 h = __floats2half2_rn(lo, hi);
    return *reinterpret_cast<uint32_t*>(&h);
}

// ---------------------------------------------------------------------------
// Weight prep: transpose + fp16. out[n*K + k] = half(in[k*N + n])
// grid (N/32, K/32), block (32, 8)
// ---------------------------------------------------------------------------
__global__ __launch_bounds__(256)
void wprep_kernel(const float* __restrict__ in, __half* __restrict__ out, int K, int N)
{
    __shared__ float t[32][33];
    int n0 = blockIdx.x * 32, k0 = blockIdx.y * 32;
    int tx = threadIdx.x, ty = threadIdx.y;
    #pragma unroll
    for (int j = 0; j < 4; j++) {
        int kk = j * 8 + ty;
        t[kk][tx] = in[(size_t)(k0 + kk) * N + n0 + tx];
    }
    __syncthreads();
    #pragma unroll
    for (int j = 0; j < 4; j++) {
        int nn = j * 8 + ty;
        out[(size_t)(n0 + nn) * K + k0 + tx] = __float2half_rn(t[tx][nn]);
    }
}

// ---------------------------------------------------------------------------
// LayerNorm: fp32 in, half out (consumed only as GEMM A operand)
// ---------------------------------------------------------------------------
__global__ __launch_bounds__(256)
void ln_kernel(const float* __restrict__ x, const float* __restrict__ gam,
               const float* __restrict__ bet, __half* __restrict__ out)
{
    int row = blockIdx.x;
    int tid = threadIdx.x;
    const float* xr = x + (size_t)row * CDIM;

    float v0 = xr[tid], v1 = xr[tid + 256], v2 = xr[tid + 512];

    __shared__ float red[8];
    __shared__ float mu_s, rs_s;

    float s = v0 + v1 + v2;
    #pragma unroll
    for (int off = 16; off > 0; off >>= 1) s += __shfl_xor_sync(0xffffffffu, s, off);
    if ((tid & 31) == 0) red[tid >> 5] = s;
    __syncthreads();
    if (tid == 0) {
        float t = 0.f;
        #pragma unroll
        for (int i = 0; i < 8; i++) t += red[i];
        mu_s = t * (1.0f / CDIM);
    }
    __syncthreads();
    float mu = mu_s;
    float d0 = v0 - mu, d1 = v1 - mu, d2 = v2 - mu;

    float q = d0*d0 + d1*d1 + d2*d2;
    #pragma unroll
    for (int off = 16; off > 0; off >>= 1) q += __shfl_xor_sync(0xffffffffu, q, off);
    __syncthreads();
    if ((tid & 31) == 0) red[tid >> 5] = q;
    __syncthreads();
    if (tid == 0) {
        float t = 0.f;
        #pragma unroll
        for (int i = 0; i < 8; i++) t += red[i];
        rs_s = rsqrtf(t * (1.0f / CDIM) + LN_EPS);
    }
    __syncthreads();
    float rs = rs_s;

    __half* orow = out + (size_t)row * CDIM;
    orow[tid      ] = __float2half_rn(d0 * rs * gam[tid      ] + bet[tid      ]);
    orow[tid + 256] = __float2half_rn(d1 * rs * gam[tid + 256] + bet[tid + 256]);
    orow[tid + 512] = __float2half_rn(d2 * rs * gam[tid + 512] + bet[tid + 512]);
}

// ---------------------------------------------------------------------------
// FP16 tensor-core GEMM: C[M,N] = A[M,K] @ Bt[N,K]^T + bias (+GELU)(+resid)
// 128x128x64 tile, 8 warps (64x32 warp tiles), mma.m16n8k16.f16.f32,
// 3-stage cp.async pipeline, 72-half padded smem (conflict-free half2 frags).
// M%128==0, N%128==0, K%64==0.
// ---------------------------------------------------------------------------
#define BK 64
#define ROWW 36                      // words per smem row (72 halves = 144 B)
#define STAGE_W 9216                 // words per stage: (128+128)*36
#define BOFF_W 4608                  // B offset within stage (words)
#define GEMM_SMEM_BYTES (3 * STAGE_W * 4)   // 110592

template<bool DO_GELU, bool DO_RESID, bool OUT_HALF>
__global__ __launch_bounds__(256, 2)
void hgemm(const __half* __restrict__ A, const __half* __restrict__ Bt,
           const float* __restrict__ bias, const float* __restrict__ resid,
           void* __restrict__ Cv, int M, int N, int K)
{
    extern __shared__ uint32_t smw[];

    int tid  = threadIdx.x;
    int warp = tid >> 5;
    int lane = tid & 31;
    int gr   = lane >> 2;          // 0..7
    int t4   = lane & 3;           // 0..3
    int row0 = blockIdx.y * 128;
    int col0 = blockIdx.x * 128;
    int wm   = (warp >> 2) * 64;   // 0 or 64
    int wn   = (warp & 3) * 32;    // 0,32,64,96

    float acc[4][4][4];
    #pragma unroll
    for (int i = 0; i < 4; i++)
        #pragma unroll
        for (int j = 0; j < 4; j++)
            #pragma unroll
            for (int r = 0; r < 4; r++) acc[i][j][r] = 0.f;

    int ldr = tid >> 3;            // 0..31 ... combined below
    int ldc = tid & 7;             // chunk 0..7

    auto load_tiles = [&](int st, int kt) {
        int k0 = kt * BK;
        const __half* Ab = A  + (size_t)row0 * K + k0;
        const __half* Bb = Bt + (size_t)col0 * K + k0;
        uint32_t* sa = &smw[st * STAGE_W];
        uint32_t* sb = &smw[st * STAGE_W + BOFF_W];
        #pragma unroll
        for (int i = 0; i < 4; i++) {
            int r = ldr + i * 32;                 // 0..127
            cpasync16(&sa[r * ROWW + ldc * 4], Ab + (size_t)r * K + ldc * 8);
            cpasync16(&sb[r * ROWW + ldc * 4], Bb + (size_t)r * K + ldc * 8);
        }
        asm volatile("cp.async.commit_group;");
    };

    int KT = K / BK;
    load_tiles(0, 0);
    load_tiles(1, 1);

    for (int kt = 0; kt < KT; kt++) {
        if (kt + 1 < KT) asm volatile("cp.async.wait_group 1;" ::: "memory");
        else             asm volatile("cp.async.wait_group 0;" ::: "memory");
        __syncthreads();
        if (kt + 2 < KT) load_tiles((kt + 2) % 3, kt + 2);

        const uint32_t* st = &smw[(kt % 3) * STAGE_W];
        #pragma unroll
        for (int ks = 0; ks < 4; ks++) {
            int kw = ks * 8 + t4;
            uint32_t af[4][4], bf[4][2];
            #pragma unroll
            for (int i = 0; i < 4; i++) {
                int base = (wm + i * 16 + gr) * ROWW + kw;
                af[i][0] = st[base];
                af[i][1] = st[base + 8 * ROWW];
                af[i][2] = st[base + 4];
                af[i][3] = st[base + 8 * ROWW + 4];
            }
            #pragma unroll
            for (int j = 0; j < 4; j++) {
                int base = BOFF_W + (wn + j * 8 + gr) * ROWW + kw;
                bf[j][0] = st[base];
                bf[j][1] = st[base + 4];
            }
            #pragma unroll
            for (int i = 0; i < 4; i++)
                #pragma unroll
                for (int j = 0; j < 4; j++)
                    mma_f16(acc[i][j], af[i], bf[j]);
        }
    }

    // Epilogue
    #pragma unroll
    for (int i = 0; i < 4; i++) {
        int r0 = row0 + wm + i * 16 + gr;
        #pragma unroll
        for (int j = 0; j < 4; j++) {
            int cc = col0 + wn + j * 8 + 2 * t4;
            float2 bb = *(const float2*)&bias[cc];
            float v0 = acc[i][j][0] + bb.x;
            float v1 = acc[i][j][1] + bb.y;
            float v2 = acc[i][j][2] + bb.x;
            float v3 = acc[i][j][3] + bb.y;
            if (DO_GELU) {
                v0 = 0.5f * v0 * (1.0f + erff(v0 * 0.70710678118654752f));
                v1 = 0.5f * v1 * (1.0f + erff(v1 * 0.70710678118654752f));
                v2 = 0.5f * v2 * (1.0f + erff(v2 * 0.70710678118654752f));
                v3 = 0.5f * v3 * (1.0f + erff(v3 * 0.70710678118654752f));
            }
            size_t o0 = (size_t)r0 * N + cc;
            size_t o1 = (size_t)(r0 + 8) * N + cc;
            if (DO_RESID) {
                float2 ra = *(const float2*)&resid[o0];
                float2 rb = *(const float2*)&resid[o1];
                v0 += ra.x; v1 += ra.y; v2 += rb.x; v3 += rb.y;
            }
            if (OUT_HALF) {
                uint32_t* C = (uint32_t*)Cv;
                C[o0 >> 1] = h2pack(v0, v1);
                C[o1 >> 1] = h2pack(v2, v3);
            } else {
                float* C = (float*)Cv;
                *(float2*)&C[o0] = make_float2(v0, v1);
                *(float2*)&C[o1] = make_float2(v2, v3);
            }
        }
    }
}

// ---------------------------------------------------------------------------
// FP16 tensor-core flash attention. Block = 64 queries x 1 head, 4 warps.
// Probabilities never leave registers (S C-frag == PV A-frag layout).
// Smem: Q[64][72]h, K[64][72]h, Vt[d=64][72]h (keys contiguous).
// ---------------------------------------------------------------------------
#define AQ_W 0
#define AK_W 2304
#define AV_W 4608
#define ATTN_SMEM (3 * 2304 * 4)    // 27648 B

__global__ __launch_bounds__(128)
void attn_h(const __half* __restrict__ qkv, __half* __restrict__ outp)
{
    extern __shared__ uint32_t smw[];

    int tid  = threadIdx.x;
    int warp = tid >> 5;
    int lane = tid & 31;
    int gr   = lane >> 2;
    int t4   = lane & 3;
    int qb   = blockIdx.x * 64;
    int b    = blockIdx.y / NHEADS;
    int h    = blockIdx.y % NHEADS;
    const __half* base = qkv + (size_t)b * SEQ * C3 + h * HDIM;

    const float SCL = 0.125f * 1.4426950408889634f;   // scale * log2(e)

    // Load Q tile (natural layout, 16B chunks)
    #pragma unroll
    for (int i = 0; i < 4; i++) {
        int idx = tid + i * 128;
        int r = idx >> 3, c8 = idx & 7;
        uint4 v = *(const uint4*)(base + (size_t)(qb + r) * C3 + c8 * 8);
        *(uint4*)&smw[AQ_W + r * ROWW + c8 * 4] = v;
    }
    __syncthreads();

    // Hoist Q fragments (4 k-steps over d=64)
    uint32_t qf[4][4];
    #pragma unroll
    for (int ks = 0; ks < 4; ks++) {
        int bidx = AQ_W + (16 * warp + gr) * ROWW + ks * 8 + t4;
        qf[ks][0] = smw[bidx];
        qf[ks][1] = smw[bidx + 8 * ROWW];
        qf[ks][2] = smw[bidx + 4];
        qf[ks][3] = smw[bidx + 8 * ROWW + 4];
    }

    float m1 = -1e30f, m2 = -1e30f, l1 = 0.f, l2 = 0.f;
    float oc[8][4];
    #pragma unroll
    for (int j = 0; j < 8; j++)
        #pragma unroll
        for (int r = 0; r < 4; r++) oc[j][r] = 0.f;

    for (int kt = 0; kt < SEQ / 64; kt++) {
        __syncthreads();   // all warps done reading K/V of previous tile
        // K tile: natural [key][d]
        #pragma unroll
        for (int i = 0; i < 4; i++) {
            int idx = tid + i * 128;
            int r = idx >> 3, c8 = idx & 7;
            uint4 v = *(const uint4*)(base + (size_t)(kt * 64 + r) * C3 + CDIM + c8 * 8);
            *(uint4*)&smw[AK_W + r * ROWW + c8 * 4] = v;
        }
        // V tile transposed: Vt[d][key], key pairs packed per word
        #pragma unroll
        for (int i = 0; i < 2; i++) {
            int idx = tid + i * 128;         // 0..255
            int c8 = idx >> 5;               // 0..7  (d chunk)
            int rp = idx & 31;               // key pair 0..31
            const __half* s0 = base + (size_t)(kt * 64 + 2 * rp) * C3 + 2 * CDIM + c8 * 8;
            uint4 va = *(const uint4*)s0;
            uint4 vb = *(const uint4*)(s0 + C3);
            __half a[8], c[8];
            *(uint4*)a = va; *(uint4*)c = vb;
            #pragma unroll
            for (int j = 0; j < 8; j++) {
                __half2 p = __halves2half2(a[j], c[j]);
                smw[AV_W + (c8 * 8 + j) * ROWW + rp] = *reinterpret_cast<uint32_t*>(&p);
            }
        }
        __syncthreads();

        // S = Q @ K^T  (fp32 acc)
        float sc[8][4];
        #pragma unroll
        for (int j = 0; j < 8; j++)
            #pragma unroll
            for (int r = 0; r < 4; r++) sc[j][r] = 0.f;

        #pragma unroll
        for (int ks = 0; ks < 4; ks++) {
            int kw = ks * 8 + t4;
            uint32_t kf[8][2];
            #pragma unroll
            for (int j = 0; j < 8; j++) {
                int bidx = AK_W + (j * 8 + gr) * ROWW + kw;
                kf[j][0] = smw[bidx];
                kf[j][1] = smw[bidx + 4];
            }
            #pragma unroll
            for (int j = 0; j < 8; j++)
                mma_f16(sc[j], qf[ks], kf[j]);
        }
        #pragma unroll
        for (int j = 0; j < 8; j++) {
            sc[j][0] *= SCL; sc[j][1] *= SCL; sc[j][2] *= SCL; sc[j][3] *= SCL;
        }

        // Online softmax in log2 domain; P stays in registers.
        float mx1 = -1e30f, mx2 = -1e30f;
        #pragma unroll
        for (int j = 0; j < 8; j++) {
            mx1 = fmaxf(mx1, fmaxf(sc[j][0], sc[j][1]));
            mx2 = fmaxf(mx2, fmaxf(sc[j][2], sc[j][3]));
        }
        mx1 = fmaxf(mx1, __shfl_xor_sync(0xffffffffu, mx1, 1));
        mx1 = fmaxf(mx1, __shfl_xor_sync(0xffffffffu, mx1, 2));
        mx2 = fmaxf(mx2, __shfl_xor_sync(0xffffffffu, mx2, 1));
        mx2 = fmaxf(mx2, __shfl_xor_sync(0xffffffffu, mx2, 2));

        float nm1 = fmaxf(m1, mx1), nm2 = fmaxf(m2, mx2);
        float a1 = ex2f(m1 - nm1), a2 = ex2f(m2 - nm2);
        float s1 = 0.f, s2 = 0.f;
        uint32_t ph[8][2];
        #pragma unroll
        for (int j = 0; j < 8; j++) {
            float p0 = ex2f(sc[j][0] - nm1);
            float p1 = ex2f(sc[j][1] - nm1);
            float p2 = ex2f(sc[j][2] - nm2);
            float p3 = ex2f(sc[j][3] - nm2);
            s1 += p0 + p1; s2 += p2 + p3;
            ph[j][0] = h2pack(p0, p1);
            ph[j][1] = h2pack(p2, p3);
        }
        s1 += __shfl_xor_sync(0xffffffffu, s1, 1);
        s1 += __shfl_xor_sync(0xffffffffu, s1, 2);
        s2 += __shfl_xor_sync(0xffffffffu, s2, 1);
        s2 += __shfl_xor_sync(0xffffffffu, s2, 2);
        l1 = l1 * a1 + s1;  l2 = l2 * a2 + s2;
        m1 = nm1;           m2 = nm2;
        #pragma unroll
        for (int j = 0; j < 8; j++) {
            oc[j][0] *= a1; oc[j][1] *= a1;
            oc[j][2] *= a2; oc[j][3] *= a2;
        }

        // O += P @ V  (A-frag = S C-frag, already in regs)
        #pragma unroll
        for (int ks = 0; ks < 4; ks++) {
            uint32_t pf[4] = { ph[2*ks][0], ph[2*ks][1], ph[2*ks+1][0], ph[2*ks+1][1] };
            int kw = ks * 8 + t4;
            uint32_t vf[8][2];
            #pragma unroll
            for (int j = 0; j < 8; j++) {
                int bidx = AV_W + (j * 8 + gr) * ROWW + kw;
                vf[j][0] = smw[bidx];
                vf[j][1] = smw[bidx + 4];
            }
            #pragma unroll
            for (int j = 0; j < 8; j++)
                mma_f16(oc[j], pf, vf[j]);
        }
    }

    // Epilogue: normalize, write half
    float il1 = 1.0f / l1, il2 = 1.0f / l2;
    int r1 = qb + 16 * warp + gr;
    uint32_t* o32 = (uint32_t*)outp;
    #pragma unroll
    for (int j = 0; j < 8; j++) {
        int cc = h * HDIM + j * 8 + 2 * t4;
        size_t o0 = ((size_t)(b * SEQ + r1) * CDIM + cc) >> 1;
        size_t o1 = o0 + 4 * CDIM;   // +8 rows (in half2 units)
        o32[o0] = h2pack(oc[j][0] * il1, oc[j][1] * il1);
        o32[o1] = h2pack(oc[j][2] * il2, oc[j][3] * il2);
    }
}

// ---------------------------------------------------------------------------
// Launch
// ---------------------------------------------------------------------------
extern "C" void kernel_launch(void* const* d_in, const int* in_sizes, int n_in,
                              void* d_out, int out_size)
{
    const float* x      = (const float*)d_in[0];
    const float* ln1_g  = (const float*)d_in[1];
    const float* ln1_b  = (const float*)d_in[2];
    const float* qkv_w  = (const float*)d_in[3];
    const float* qkv_b  = (const float*)d_in[4];
    const float* proj_w = (const float*)d_in[5];
    const float* proj_b = (const float*)d_in[6];
    const float* ln2_g  = (const float*)d_in[7];
    const float* ln2_b  = (const float*)d_in[8];
    const float* fc1_w  = (const float*)d_in[9];
    const float* fc1_b  = (const float*)d_in[10];
    const float* fc2_w  = (const float*)d_in[11];
    const float* fc2_b  = (const float*)d_in[12];
    float* out = (float*)d_out;

    __half *p_xn1, *p_qkv, *p_attn, *p_hn, *p_h1;
    __half *p_wq, *p_wp, *p_w1, *p_w2;
    float  *p_x2;
    cudaGetSymbolAddress((void**)&p_xn1,  g_xn1);
    cudaGetSymbolAddress((void**)&p_qkv,  g_qkv);
    cudaGetSymbolAddress((void**)&p_attn, g_attn);
    cudaGetSymbolAddress((void**)&p_x2,   g_x2);
    cudaGetSymbolAddress((void**)&p_hn,   g_hn);
    cudaGetSymbolAddress((void**)&p_h1,   g_h1);
    cudaGetSymbolAddress((void**)&p_wq,   g_wq);
    cudaGetSymbolAddress((void**)&p_wp,   g_wp);
    cudaGetSymbolAddress((void**)&p_w1,   g_w1);
    cudaGetSymbolAddress((void**)&p_w2,   g_w2);

    cudaFuncSetAttribute(attn_h,
                         cudaFuncAttributeMaxDynamicSharedMemorySize, ATTN_SMEM);
    cudaFuncSetAttribute(hgemm<false,false,true>,
                         cudaFuncAttributeMaxDynamicSharedMemorySize, GEMM_SMEM_BYTES);
    cudaFuncSetAttribute(hgemm<false,true,false>,
                         cudaFuncAttributeMaxDynamicSharedMemorySize, GEMM_SMEM_BYTES);
    cudaFuncSetAttribute(hgemm<true,false,true>,
                         cudaFuncAttributeMaxDynamicSharedMemorySize, GEMM_SMEM_BYTES);

    // 0) Weight prep: transpose + fp16
    wprep_kernel<<<dim3(C3/32,   CDIM/32), dim3(32,8)>>>(qkv_w,  p_wq, CDIM, C3);
    wprep_kernel<<<dim3(CDIM/32, CDIM/32), dim3(32,8)>>>(proj_w, p_wp, CDIM, CDIM);
    wprep_kernel<<<dim3(HID/32,  CDIM/32), dim3(32,8)>>>(fc1_w,  p_w1, CDIM, HID);
    wprep_kernel<<<dim3(CDIM/32, HID/32 ), dim3(32,8)>>>(fc2_w,  p_w2, HID,  CDIM);

    // 1) LN1
    ln_kernel<<<TOKENS, 256>>>(x, ln1_g, ln1_b, p_xn1);

    // 2) qkv = xn1 @ qkv_w + qkv_b  (half out)
    hgemm<false,false,true><<<dim3(C3/128, TOKENS/128), 256, GEMM_SMEM_BYTES>>>(
        p_xn1, p_wq, qkv_b, nullptr, p_qkv, TOKENS, C3, CDIM);

    // 3) attention (half out)
    attn_h<<<dim3(SEQ/64, BATCH*NHEADS), 128, ATTN_SMEM>>>(p_qkv, p_attn);

    // 4) x2 = x + attn @ proj_w + proj_b  (fp32 out)
    hgemm<false,true,false><<<dim3(CDIM/128, TOKENS/128), 256, GEMM_SMEM_BYTES>>>(
        p_attn, p_wp, proj_b, x, p_x2, TOKENS, CDIM, CDIM);

    // 5) LN2
    ln_kernel<<<TOKENS, 256>>>(p_x2, ln2_g, ln2_b, p_hn);

    // 6) h1 = gelu(hn @ fc1_w + fc1_b)  (half out)
    hgemm<true,false,true><<<dim3(HID/128, TOKENS/128), 256, GEMM_SMEM_BYTES>>>(
        p_hn, p_w1, fc1_b, nullptr, p_h1, TOKENS, HID, CDIM);

    // 7) out = x2 + h1 @ fc2_w + fc2_b  (fp32 out)
    hgemm<false,true,false><<<dim3(CDIM/128, TOKENS/128), 256, GEMM_SMEM_BYTES>>>(
        p_h1, p_w2, fc2_b, p_x2, out, TOKENS, CDIM, HID);
}